// round 1
// baseline (speedup 1.0000x reference)
#include <cuda_runtime.h>
#include <math_constants.h>

// ============================================================
// ChamferLoss: N=M=16384, D=3.
//   loss = ( sum_i min_j ||a_i-b_j||  +  sum_j min_i ||b_j-a_i|| ) / 1000
// Strategy: brute-force pair distances with SMEM-resident target tiles.
// Track min SQUARED distance (sqrt is monotone), sqrt once per point.
// ============================================================

#define THREADS 128
#define QPT 8            // query points per thread (register-resident)
#define TCHUNK 2048      // target points per SMEM tile (24 KB)
#define MAXPTS 16384

// scratch: per-point min squared distance, both directions
__device__ float g_minsq[2 * MAXPTS];

__global__ void init_minsq_kernel(int total) {
    int i = blockIdx.x * blockDim.x + threadIdx.x;
    if (i < total) g_minsq[i] = CUDART_INF_F;
}

__global__ void __launch_bounds__(THREADS)
chamfer_min_kernel(const float* __restrict__ A, const float* __restrict__ B,
                   int N, int M)
{
    // blockIdx.z selects direction: 0 => queries=A targets=B, 1 => swapped
    const float* __restrict__ P = (blockIdx.z == 0) ? A : B;
    const float* __restrict__ T = (blockIdx.z == 0) ? B : A;
    const int nq = (blockIdx.z == 0) ? N : M;
    const int nt = (blockIdx.z == 0) ? M : N;
    float* minsq = g_minsq + blockIdx.z * MAXPTS;

    __shared__ float s[TCHUNK * 3];

    const int tbase = blockIdx.y * TCHUNK;
    if (tbase >= nt) return;
    const int nload = min(TCHUNK, nt - tbase);

    // coalesced load of target tile (AoS float triplets, read flat)
    for (int k = threadIdx.x; k < nload * 3; k += THREADS)
        s[k] = T[tbase * 3 + k];
    __syncthreads();

    // register-resident query points
    const int qbase = blockIdx.x * (THREADS * QPT) + threadIdx.x;
    float qx[QPT], qy[QPT], qz[QPT], m[QPT];
    #pragma unroll
    for (int q = 0; q < QPT; q++) {
        int qi = qbase + q * THREADS;
        bool v = (qi < nq);
        int base = v ? qi * 3 : 0;
        qx[q] = P[base + 0];
        qy[q] = P[base + 1];
        qz[q] = P[base + 2];
        m[q] = CUDART_INF_F;
    }

    // main loop: one broadcast SMEM read serves QPT register queries
    #pragma unroll 2
    for (int j = 0; j < nload; j++) {
        const float bx = s[3 * j + 0];
        const float by = s[3 * j + 1];
        const float bz = s[3 * j + 2];
        #pragma unroll
        for (int q = 0; q < QPT; q++) {
            float dx = qx[q] - bx;
            float dy = qy[q] - by;
            float dz = qz[q] - bz;
            float d = fmaf(dx, dx, fmaf(dy, dy, dz * dz));
            m[q] = fminf(m[q], d);
        }
    }

    // combine partial mins across target-chunk blocks.
    // squared distances are >= 0, so integer compare == float compare.
    #pragma unroll
    for (int q = 0; q < QPT; q++) {
        int qi = qbase + q * THREADS;
        if (qi < nq)
            atomicMin(reinterpret_cast<int*>(&minsq[qi]), __float_as_int(m[q]));
    }
}

__global__ void __launch_bounds__(1024)
chamfer_reduce_kernel(float* __restrict__ out, int total)
{
    __shared__ float ssum[32];
    float acc = 0.0f;
    for (int i = threadIdx.x; i < total; i += 1024)
        acc += sqrtf(g_minsq[i]);

    #pragma unroll
    for (int o = 16; o > 0; o >>= 1)
        acc += __shfl_down_sync(0xFFFFFFFFu, acc, o);
    if ((threadIdx.x & 31) == 0) ssum[threadIdx.x >> 5] = acc;
    __syncthreads();
    if (threadIdx.x < 32) {
        float v = ssum[threadIdx.x];
        #pragma unroll
        for (int o = 16; o > 0; o >>= 1)
            v += __shfl_down_sync(0xFFFFFFFFu, v, o);
        if (threadIdx.x == 0) out[0] = v * 0.001f;
    }
}

extern "C" void kernel_launch(void* const* d_in, const int* in_sizes, int n_in,
                              void* d_out, int out_size)
{
    const float* A = (const float*)d_in[0];   // target_pc [N,3]
    const float* B = (const float*)d_in[1];   // output_pc [M,3]
    const int N = in_sizes[0] / 3;
    const int M = in_sizes[1] / 3;

    // init scratch mins to +inf
    init_minsq_kernel<<<(2 * MAXPTS + 255) / 256, 256>>>(2 * MAXPTS);

    const int qspan = THREADS * QPT;                 // 1024 queries per block
    const int maxn = (N > M) ? N : M;
    dim3 grid((maxn + qspan - 1) / qspan,            // 16
              (maxn + TCHUNK - 1) / TCHUNK,          // 8
              2);                                    // both directions
    chamfer_min_kernel<<<grid, THREADS>>>(A, B, N, M);

    chamfer_reduce_kernel<<<1, 1024>>>((float*)d_out, N + M);
}

// round 2
// speedup vs baseline: 1.5823x; 1.5823x over previous
#include <cuda_runtime.h>
#include <math_constants.h>

// ============================================================
// ChamferLoss: N=M=16384, D=3.
// d^2(q,b) = |q|^2 - 2*(q.b - 0.5|b|^2)  -> 3 FMA/pair, running MAX of s.
// Packed fma.rn.f32x2 handles 2 query points per op -> 1.5 fma-issues/pair.
// Targets stored in SMEM pre-duplicated: {bx,bx},{by,by},{bz,bz},{nhb,nhb}.
// ============================================================

#define THREADS 256
#define QPT 8            // query points per thread (4 packed pairs)
#define TCHUNK 1024      // target points per SMEM tile (32 KB duplicated)
#define MAXPTS 16384

__device__ float g_minsq[2 * MAXPTS];

__device__ __forceinline__ unsigned long long pack2(float lo, float hi) {
    unsigned long long r;
    asm("mov.b64 %0, {%1, %2};" : "=l"(r) : "f"(lo), "f"(hi));
    return r;
}
__device__ __forceinline__ void unpack2(unsigned long long v, float& lo, float& hi) {
    asm("mov.b64 {%0, %1}, %2;" : "=f"(lo), "=f"(hi) : "l"(v));
}
__device__ __forceinline__ unsigned long long fma2(unsigned long long a,
                                                   unsigned long long b,
                                                   unsigned long long c) {
    unsigned long long d;
    asm("fma.rn.f32x2 %0, %1, %2, %3;" : "=l"(d) : "l"(a), "l"(b), "l"(c));
    return d;
}

__global__ void init_minsq_kernel(int total) {
    int i = blockIdx.x * blockDim.x + threadIdx.x;
    if (i < total) g_minsq[i] = CUDART_INF_F;
}

__global__ void __launch_bounds__(THREADS)
chamfer_min_kernel(const float* __restrict__ A, const float* __restrict__ B,
                   int N, int M)
{
    const float* __restrict__ P = (blockIdx.z == 0) ? A : B;
    const float* __restrict__ T = (blockIdx.z == 0) ? B : A;
    const int nq = (blockIdx.z == 0) ? N : M;
    const int nt = (blockIdx.z == 0) ? M : N;
    float* minsq = g_minsq + blockIdx.z * MAXPTS;

    // per target point: {bx,bx},{by,by} | {bz,bz},{nhb,nhb}  (2x ulonglong2)
    __shared__ ulonglong2 sv[TCHUNK * 2];

    const int tbase = blockIdx.y * TCHUNK;
    if (tbase >= nt) return;
    const int nload = min(TCHUNK, nt - tbase);

    for (int j = threadIdx.x; j < nload; j += THREADS) {
        float bx = T[(tbase + j) * 3 + 0];
        float by = T[(tbase + j) * 3 + 1];
        float bz = T[(tbase + j) * 3 + 2];
        float nhb = -0.5f * fmaf(bx, bx, fmaf(by, by, bz * bz));
        sv[2 * j]     = make_ulonglong2(pack2(bx, bx), pack2(by, by));
        sv[2 * j + 1] = make_ulonglong2(pack2(bz, bz), pack2(nhb, nhb));
    }
    __syncthreads();

    // register-resident queries, packed in pairs
    const int qbase = blockIdx.x * (THREADS * QPT) + threadIdx.x;
    float qfx[QPT], qfy[QPT], qfz[QPT], qn[QPT], ms[QPT];
    #pragma unroll
    for (int q = 0; q < QPT; q++) {
        int qi = qbase + q * THREADS;
        int base = (qi < nq ? qi : 0) * 3;
        qfx[q] = P[base + 0];
        qfy[q] = P[base + 1];
        qfz[q] = P[base + 2];
        qn[q] = fmaf(qfx[q], qfx[q], fmaf(qfy[q], qfy[q], qfz[q] * qfz[q]));
        ms[q] = -CUDART_INF_F;
    }
    unsigned long long qx[QPT / 2], qy[QPT / 2], qz[QPT / 2];
    #pragma unroll
    for (int p = 0; p < QPT / 2; p++) {
        qx[p] = pack2(qfx[2 * p], qfx[2 * p + 1]);
        qy[p] = pack2(qfy[2 * p], qfy[2 * p + 1]);
        qz[p] = pack2(qfz[2 * p], qfz[2 * p + 1]);
    }

    // main loop: 2 broadcast LDS.128 + 12 FFMA2 + 8 FMNMX per target
    #pragma unroll 2
    for (int j = 0; j < nload; j++) {
        const ulonglong2 v0 = sv[2 * j];       // {bx,bx},{by,by}
        const ulonglong2 v1 = sv[2 * j + 1];   // {bz,bz},{nhb,nhb}
        #pragma unroll
        for (int p = 0; p < QPT / 2; p++) {
            unsigned long long t = fma2(qz[p], v1.x, v1.y);  // qz*bz - 0.5|b|^2
            t = fma2(qy[p], v0.y, t);
            t = fma2(qx[p], v0.x, t);                        // s = q.b - 0.5|b|^2
            float s0, s1;
            unpack2(t, s0, s1);
            ms[2 * p]     = fmaxf(ms[2 * p],     s0);
            ms[2 * p + 1] = fmaxf(ms[2 * p + 1], s1);
        }
    }

    // d^2 = max(|q|^2 - 2*max_s, 0); combine across chunk-blocks (nonneg => int min)
    #pragma unroll
    for (int q = 0; q < QPT; q++) {
        int qi = qbase + q * THREADS;
        if (qi < nq) {
            float dsq = fmaxf(fmaf(-2.0f, ms[q], qn[q]), 0.0f);
            atomicMin(reinterpret_cast<int*>(&minsq[qi]), __float_as_int(dsq));
        }
    }
}

__global__ void __launch_bounds__(1024)
chamfer_reduce_kernel(float* __restrict__ out, int total)
{
    __shared__ float ssum[32];
    float acc = 0.0f;
    for (int i = threadIdx.x; i < total; i += 1024)
        acc += sqrtf(g_minsq[i]);

    #pragma unroll
    for (int o = 16; o > 0; o >>= 1)
        acc += __shfl_down_sync(0xFFFFFFFFu, acc, o);
    if ((threadIdx.x & 31) == 0) ssum[threadIdx.x >> 5] = acc;
    __syncthreads();
    if (threadIdx.x < 32) {
        float v = ssum[threadIdx.x];
        #pragma unroll
        for (int o = 16; o > 0; o >>= 1)
            v += __shfl_down_sync(0xFFFFFFFFu, v, o);
        if (threadIdx.x == 0) out[0] = v * 0.001f;
    }
}

extern "C" void kernel_launch(void* const* d_in, const int* in_sizes, int n_in,
                              void* d_out, int out_size)
{
    const float* A = (const float*)d_in[0];   // target_pc [N,3]
    const float* B = (const float*)d_in[1];   // output_pc [M,3]
    const int N = in_sizes[0] / 3;
    const int M = in_sizes[1] / 3;

    init_minsq_kernel<<<(2 * MAXPTS + 255) / 256, 256>>>(2 * MAXPTS);

    const int qspan = THREADS * QPT;                 // 2048 queries per block
    const int maxn = (N > M) ? N : M;
    dim3 grid((maxn + qspan - 1) / qspan,            // 8
              (maxn + TCHUNK - 1) / TCHUNK,          // 16
              2);                                    // both directions
    chamfer_min_kernel<<<grid, THREADS>>>(A, B, N, M);

    chamfer_reduce_kernel<<<1, 1024>>>((float*)d_out, N + M);
}